// round 2
// baseline (speedup 1.0000x reference)
#include <cuda_runtime.h>

#define B_   2
#define T_   2048
#define C_   768
#define H_   12
#define DH_  64
#define M_   (B_ * T_)        // 4096 token rows
#define N3C_ (3 * C_)         // 2304

// Scratch (allocation-free rule: device globals)
__device__ float g_qkv[M_ * N3C_];   // [4096, 2304]  q|k|v interleaved per row
__device__ float g_att[M_ * C_];     // [4096, 768]   attention output, [b,t,h*dh]

// ---------------------------------------------------------------------------
// SGEMM: C[M,N] = A[M,K] @ B[K,N], row-major, 128x128 tile, BK=8, 8x8/thread
// M%128==0, N%128==0, K%8==0 (holds for all our shapes)
// ---------------------------------------------------------------------------
__global__ __launch_bounds__(256, 2)
void sgemm_kernel(const float* __restrict__ A, const float* __restrict__ Bm,
                  float* __restrict__ C, int M, int N, int K)
{
    __shared__ float As[8][128];
    __shared__ float Bs[8][128];

    const int tid  = threadIdx.x;
    const int tx   = tid & 15;
    const int ty   = tid >> 4;
    const int row0 = blockIdx.y * 128;
    const int col0 = blockIdx.x * 128;

    const int ar = tid >> 1;          // 0..127
    const int ac = (tid & 1) * 4;     // 0 or 4
    const int br = tid >> 5;          // 0..7
    const int bc = (tid & 31) * 4;    // 0..124

    const float* Aptr = A + (size_t)(row0 + ar) * K + ac;
    const float* Bptr = Bm + (size_t)br * N + col0 + bc;

    float acc[8][8];
    #pragma unroll
    for (int i = 0; i < 8; i++)
        #pragma unroll
        for (int j = 0; j < 8; j++) acc[i][j] = 0.f;

    for (int k0 = 0; k0 < K; k0 += 8) {
        float4 av = *(const float4*)(Aptr + k0);
        float4 bv = *(const float4*)(Bptr + (size_t)k0 * N);
        __syncthreads();
        As[ac + 0][ar] = av.x;
        As[ac + 1][ar] = av.y;
        As[ac + 2][ar] = av.z;
        As[ac + 3][ar] = av.w;
        *(float4*)&Bs[br][bc] = bv;
        __syncthreads();

        #pragma unroll
        for (int kk = 0; kk < 8; kk++) {
            float4 a0 = *(float4*)&As[kk][ty * 4];
            float4 a1 = *(float4*)&As[kk][64 + ty * 4];
            float4 b0 = *(float4*)&Bs[kk][tx * 4];
            float4 b1 = *(float4*)&Bs[kk][64 + tx * 4];
            float a[8] = {a0.x, a0.y, a0.z, a0.w, a1.x, a1.y, a1.z, a1.w};
            float b[8] = {b0.x, b0.y, b0.z, b0.w, b1.x, b1.y, b1.z, b1.w};
            #pragma unroll
            for (int i = 0; i < 8; i++)
                #pragma unroll
                for (int j = 0; j < 8; j++)
                    acc[i][j] = fmaf(a[i], b[j], acc[i][j]);
        }
    }

    #pragma unroll
    for (int i = 0; i < 8; i++) {
        int r = row0 + ((i < 4) ? (ty * 4 + i) : (64 + ty * 4 + (i - 4)));
        float4 v0 = make_float4(acc[i][0], acc[i][1], acc[i][2], acc[i][3]);
        float4 v1 = make_float4(acc[i][4], acc[i][5], acc[i][6], acc[i][7]);
        *(float4*)&C[(size_t)r * N + col0 + tx * 4]      = v0;
        *(float4*)&C[(size_t)r * N + col0 + 64 + tx * 4] = v1;
    }
}

// ---------------------------------------------------------------------------
// Flash attention (causal), fp32. Grid: (T/64, B*H). 256 thr as 16x16, 4x4 tiles.
// Smem (dynamic, 51200 B):
//   QsT [64][68]  Q transposed [d][r]
//   KP  [64][68]  KsT [d][c] during S; reused as Ps [r][c] for PV
//   Vs  [64][64]  V [c][d]
// ---------------------------------------------------------------------------
#define FLASH_SMEM_BYTES ((64 * 68 * 2 + 64 * 64) * 4)

__global__ __launch_bounds__(256)
void flash_kernel()
{
    extern __shared__ float sm[];
    float* QsT = sm;
    float* KP  = sm + 64 * 68;
    float* Vs  = sm + 2 * 64 * 68;

    const int tid = threadIdx.x;
    const int tx  = tid & 15;
    const int ty  = tid >> 4;
    const int bh  = blockIdx.y;
    const int b   = bh / H_;
    const int h   = bh % H_;
    const int qt  = (T_ / 64 - 1) - blockIdx.x;   // heavy tiles first
    const int q0  = qt * 64;
    const long rowbase = (long)b * T_;
    const int qoff = h * DH_;
    const int koff = C_ + h * DH_;
    const int voff = 2 * C_ + h * DH_;
    const float scale = 0.125f;   // DH^-0.5

    // Load Q tile transposed: QsT[d][r]
    #pragma unroll
    for (int it = 0; it < 4; it++) {
        int idx = tid + it * 256;
        int r   = idx >> 4;
        int d0  = (idx & 15) * 4;
        float4 v = *(const float4*)&g_qkv[(rowbase + q0 + r) * N3C_ + qoff + d0];
        QsT[(d0 + 0) * 68 + r] = v.x;
        QsT[(d0 + 1) * 68 + r] = v.y;
        QsT[(d0 + 2) * 68 + r] = v.z;
        QsT[(d0 + 3) * 68 + r] = v.w;
    }

    float o[4][4];
    float mrow[4], lrow[4];
    #pragma unroll
    for (int i = 0; i < 4; i++) {
        mrow[i] = -1e30f;
        lrow[i] = 0.f;
        #pragma unroll
        for (int j = 0; j < 4; j++) o[i][j] = 0.f;
    }

    for (int kt = 0; kt <= qt; kt++) {
        const int k0 = kt * 64;
        __syncthreads();   // previous PV reads of KP/Vs complete

        // Load K transposed (KP as KsT[d][c]) and V natural (Vs[c][d])
        #pragma unroll
        for (int it = 0; it < 4; it++) {
            int idx = tid + it * 256;
            int c   = idx >> 4;
            int d0  = (idx & 15) * 4;
            long grow = (rowbase + k0 + c) * N3C_;
            float4 kv = *(const float4*)&g_qkv[grow + koff + d0];
            KP[(d0 + 0) * 68 + c] = kv.x;
            KP[(d0 + 1) * 68 + c] = kv.y;
            KP[(d0 + 2) * 68 + c] = kv.z;
            KP[(d0 + 3) * 68 + c] = kv.w;
            *(float4*)&Vs[c * 64 + d0] = *(const float4*)&g_qkv[grow + voff + d0];
        }
        __syncthreads();

        // S = Q @ K^T (4x4 per thread)
        float s[4][4];
        #pragma unroll
        for (int i = 0; i < 4; i++)
            #pragma unroll
            for (int j = 0; j < 4; j++) s[i][j] = 0.f;

        #pragma unroll 16
        for (int d = 0; d < 64; d++) {
            float4 aq = *(float4*)&QsT[d * 68 + ty * 4];
            float4 bq = *(float4*)&KP[d * 68 + tx * 4];
            float av[4] = {aq.x, aq.y, aq.z, aq.w};
            float bv[4] = {bq.x, bq.y, bq.z, bq.w};
            #pragma unroll
            for (int i = 0; i < 4; i++)
                #pragma unroll
                for (int j = 0; j < 4; j++)
                    s[i][j] = fmaf(av[i], bv[j], s[i][j]);
        }

        // Scale + causal mask + online softmax update
        const bool diag = (kt == qt);
        #pragma unroll
        for (int i = 0; i < 4; i++) {
            #pragma unroll
            for (int j = 0; j < 4; j++) {
                s[i][j] *= scale;
                if (diag && (tx * 4 + j) > (ty * 4 + i)) s[i][j] = -1e30f;
            }
            float tm = fmaxf(fmaxf(s[i][0], s[i][1]), fmaxf(s[i][2], s[i][3]));
            #pragma unroll
            for (int off = 8; off > 0; off >>= 1)
                tm = fmaxf(tm, __shfl_xor_sync(0xffffffffu, tm, off, 16));
            float newm  = fmaxf(mrow[i], tm);
            float alpha = __expf(mrow[i] - newm);
            float ps = 0.f;
            #pragma unroll
            for (int j = 0; j < 4; j++) {
                s[i][j] = __expf(s[i][j] - newm);
                ps += s[i][j];
            }
            #pragma unroll
            for (int off = 8; off > 0; off >>= 1)
                ps += __shfl_xor_sync(0xffffffffu, ps, off, 16);
            lrow[i] = lrow[i] * alpha + ps;
            mrow[i] = newm;
            #pragma unroll
            for (int j = 0; j < 4; j++) o[i][j] *= alpha;
        }

        __syncthreads();   // all S reads of KsT done before Ps overwrite

        // Write P into KP as Ps[r][c] (stride 68, float4-aligned)
        #pragma unroll
        for (int i = 0; i < 4; i++)
            *(float4*)&KP[(ty * 4 + i) * 68 + tx * 4] =
                make_float4(s[i][0], s[i][1], s[i][2], s[i][3]);
        __syncthreads();

        // O += P @ V
        #pragma unroll 8
        for (int c = 0; c < 64; c++) {
            float av[4];
            #pragma unroll
            for (int i = 0; i < 4; i++) av[i] = KP[(ty * 4 + i) * 68 + c];
            float4 bq = *(float4*)&Vs[c * 64 + tx * 4];
            float bv[4] = {bq.x, bq.y, bq.z, bq.w};
            #pragma unroll
            for (int i = 0; i < 4; i++)
                #pragma unroll
                for (int j = 0; j < 4; j++)
                    o[i][j] = fmaf(av[i], bv[j], o[i][j]);
        }
    }

    // Normalize and write out: g_att[row][h*64 + d]
    #pragma unroll
    for (int i = 0; i < 4; i++) {
        float inv = 1.f / lrow[i];
        long r = rowbase + q0 + ty * 4 + i;
        float4 v = make_float4(o[i][0] * inv, o[i][1] * inv,
                               o[i][2] * inv, o[i][3] * inv);
        *(float4*)&g_att[r * C_ + qoff + tx * 4] = v;
    }
}

// ---------------------------------------------------------------------------
// kernel_launch: QKV gemm -> flash attention -> out gemm
// inputs: d_in[0]=x [2,2048,768], d_in[1]=Wqkv [768,2304], d_in[2]=Wout [768,768]
// ---------------------------------------------------------------------------
extern "C" void kernel_launch(void* const* d_in, const int* in_sizes, int n_in,
                              void* d_out, int out_size)
{
    const float* x    = (const float*)d_in[0];
    const float* Wqkv = (const float*)d_in[1];
    const float* Wout = (const float*)d_in[2];
    float* out = (float*)d_out;

    float *qkv_p = nullptr, *att_p = nullptr;
    cudaGetSymbolAddress((void**)&qkv_p, g_qkv);
    cudaGetSymbolAddress((void**)&att_p, g_att);

    cudaFuncSetAttribute(flash_kernel,
                         cudaFuncAttributeMaxDynamicSharedMemorySize,
                         FLASH_SMEM_BYTES);

    dim3 blk(256);
    // 1) QKV projection: [4096,768] @ [768,2304] -> g_qkv
    sgemm_kernel<<<dim3(N3C_ / 128, M_ / 128), blk>>>(x, Wqkv, qkv_p, M_, N3C_, C_);
    // 2) causal flash attention -> g_att
    flash_kernel<<<dim3(T_ / 64, B_ * H_), blk, FLASH_SMEM_BYTES>>>();
    // 3) output projection: [4096,768] @ [768,768] -> d_out
    sgemm_kernel<<<dim3(C_ / 128, M_ / 128), blk>>>(att_p, Wout, out, M_, C_, C_);
}

// round 3
// speedup vs baseline: 1.4848x; 1.4848x over previous
#include <cuda_runtime.h>
#include <cuda_bf16.h>
#include <cstdint>

#define B_   2
#define T_   2048
#define C_   768
#define H_   12
#define DH_  64
#define M_   (B_ * T_)        // 4096 token rows
#define N3C_ (3 * C_)         // 2304

// Scratch (allocation-free rule: device globals)
__device__ float g_qkv[M_ * N3C_];   // [4096, 2304]
__device__ float g_att[M_ * C_];     // [4096, 768]

// ---------------------------------------------------------------------------
// Split-bf16 helpers: a = hi + lo, each bf16. hi*hi + hi*lo + lo*hi in fp32
// accumulators recovers ~16 mantissa bits (lo*lo term ~2^-18, dropped).
// ---------------------------------------------------------------------------
__device__ __forceinline__ void split2(float x, float y, uint32_t& hi, uint32_t& lo)
{
    __nv_bfloat16 hx = __float2bfloat16_rn(x);
    __nv_bfloat16 hy = __float2bfloat16_rn(y);
    float rx = x - __bfloat162float(hx);
    float ry = y - __bfloat162float(hy);
    __nv_bfloat162 H; H.x = hx; H.y = hy;
    __nv_bfloat162 L = __floats2bfloat162_rn(rx, ry);
    hi = *reinterpret_cast<uint32_t*>(&H);
    lo = *reinterpret_cast<uint32_t*>(&L);
}

__device__ __forceinline__ void lm4(uint32_t* r, uint32_t addr)
{
    asm volatile("ldmatrix.sync.aligned.m8n8.x4.shared.b16 {%0,%1,%2,%3}, [%4];"
                 : "=r"(r[0]), "=r"(r[1]), "=r"(r[2]), "=r"(r[3]) : "r"(addr));
}

__device__ __forceinline__ void mma16816(float* d, const uint32_t* a,
                                         uint32_t b0, uint32_t b1)
{
    asm volatile("mma.sync.aligned.m16n8k16.row.col.f32.bf16.bf16.f32 "
                 "{%0,%1,%2,%3}, {%4,%5,%6,%7}, {%8,%9}, {%0,%1,%2,%3};"
                 : "+f"(d[0]), "+f"(d[1]), "+f"(d[2]), "+f"(d[3])
                 : "r"(a[0]), "r"(a[1]), "r"(a[2]), "r"(a[3]), "r"(b0), "r"(b1));
}

// ---------------------------------------------------------------------------
// Tensor-core GEMM: C[M,N] = A[M,K] @ B[K,N], fp32 in/out, split-bf16 mma.
// Block 128x128, BK=32, 8 warps (2x4), warp tile 64x32 (mt=4, nt=4).
// Smem: Ahi/Alo [128 rows][128B] (32 bf16 content + XOR chunk swizzle),
//       Bhi/Blo as BT [n][k] same layout. 64KB dynamic.
// ---------------------------------------------------------------------------
#define GEMM_SMEM 65536

__global__ __launch_bounds__(256, 2)
void gemm_bf16x2_kernel(const float* __restrict__ A, const float* __restrict__ Bm,
                        float* __restrict__ C, int M, int N, int K)
{
    extern __shared__ uint8_t smraw[];
    uint8_t* Ahi = smraw;
    uint8_t* Alo = smraw + 16384;
    uint8_t* Bhi = smraw + 32768;
    uint8_t* Blo = smraw + 49152;
    const uint32_t sbase = (uint32_t)__cvta_generic_to_shared(smraw);
    const uint32_t sAhi = sbase;
    const uint32_t sAlo = sbase + 16384;
    const uint32_t sBhi = sbase + 32768;
    const uint32_t sBlo = sbase + 49152;

    const int tid  = threadIdx.x;
    const int lane = tid & 31;
    const int warp = tid >> 5;
    const int wr   = warp >> 2;   // 0..1
    const int wc   = warp & 3;    // 0..3
    const int row0 = blockIdx.y * 128;
    const int col0 = blockIdx.x * 128;

    const int l7     = lane & 7;
    const int a_row  = wr * 64 + (lane & 15);    // + mt*16
    const int a_chi  = lane >> 4;                // chunk bit from lane
    const int b_n    = wc * 32 + ((lane >> 4) << 3) + l7;   // + np*16
    const int b_ckb  = (lane >> 3) & 1;

    float acc[4][4][4];
    #pragma unroll
    for (int i = 0; i < 4; i++)
        #pragma unroll
        for (int j = 0; j < 4; j++)
            #pragma unroll
            for (int r = 0; r < 4; r++) acc[i][j][r] = 0.f;

    for (int k0 = 0; k0 < K; k0 += 32) {
        __syncthreads();
        // ---- A tile 128x32 fp32 -> Ahi/Alo (row-major, swizzled chunks) ----
        #pragma unroll
        for (int i = 0; i < 4; i++) {
            int idx = tid + i * 256;
            int m   = idx >> 3;
            int cq  = idx & 7;                 // float4 index along k
            float4 v = *(const float4*)&A[(size_t)(row0 + m) * K + k0 + cq * 4];
            uint32_t h0, l0, h1, l1;
            split2(v.x, v.y, h0, l0);
            split2(v.z, v.w, h1, l1);
            int c = cq >> 1, hb = cq & 1;
            uint32_t off = m * 128 + (((c ^ (m & 7))) << 4) + hb * 8;
            *(uint2*)(Ahi + off) = make_uint2(h0, h1);
            *(uint2*)(Alo + off) = make_uint2(l0, l1);
        }
        // ---- B tile 32x128 fp32 -> BT[n][k] hi/lo (swizzled) ----
        #pragma unroll
        for (int i = 0; i < 4; i++) {
            int idx = tid + i * 256;
            int n   = idx & 127;
            int kq  = idx >> 7;                // 0..7, k = kq*4
            const float* bp = &Bm[(size_t)(k0 + kq * 4) * N + col0 + n];
            float f0 = bp[0];
            float f1 = bp[(size_t)N];
            float f2 = bp[(size_t)2 * N];
            float f3 = bp[(size_t)3 * N];
            uint32_t h0, l0, h1, l1;
            split2(f0, f1, h0, l0);
            split2(f2, f3, h1, l1);
            int c = kq >> 1, hb = kq & 1;
            uint32_t off = n * 128 + (((c ^ (n & 7))) << 4) + hb * 8;
            *(uint2*)(Bhi + off) = make_uint2(h0, h1);
            *(uint2*)(Blo + off) = make_uint2(l0, l1);
        }
        __syncthreads();

        #pragma unroll
        for (int ks = 0; ks < 2; ks++) {
            // B fragments: 4 ntiles, hi+lo (8+8 regs)
            uint32_t bh[8], bl[8];
            #pragma unroll
            for (int np = 0; np < 2; np++) {
                int n = b_n + np * 16;
                uint32_t boff = n * 128 + (((ks * 2 + b_ckb) ^ l7) << 4);
                lm4(&bh[np * 4], sBhi + boff);
                lm4(&bl[np * 4], sBlo + boff);
            }
            #pragma unroll
            for (int mt = 0; mt < 4; mt++) {
                int row = a_row + mt * 16;
                uint32_t aoff = row * 128 + (((ks * 2 + a_chi) ^ l7) << 4);
                uint32_t ah[4], al[4];
                lm4(ah, sAhi + aoff);
                lm4(al, sAlo + aoff);
                #pragma unroll
                for (int nt = 0; nt < 4; nt++) {
                    int bi = (nt >> 1) * 4 + (nt & 1) * 2;
                    mma16816(acc[mt][nt], ah, bh[bi], bh[bi + 1]);  // hi*hi
                    mma16816(acc[mt][nt], ah, bl[bi], bl[bi + 1]);  // hi*lo
                    mma16816(acc[mt][nt], al, bh[bi], bh[bi + 1]);  // lo*hi
                }
            }
        }
    }

    // ---- epilogue: m16n8 f32 accum layout -> global ----
    const int g  = lane >> 2;
    const int tg = lane & 3;
    #pragma unroll
    for (int mt = 0; mt < 4; mt++) {
        #pragma unroll
        for (int nt = 0; nt < 4; nt++) {
            int r = row0 + wr * 64 + mt * 16 + g;
            int c = col0 + wc * 32 + nt * 8 + tg * 2;
            *(float2*)&C[(size_t)r * N + c] =
                make_float2(acc[mt][nt][0], acc[mt][nt][1]);
            *(float2*)&C[(size_t)(r + 8) * N + c] =
                make_float2(acc[mt][nt][2], acc[mt][nt][3]);
        }
    }
}

// ---------------------------------------------------------------------------
// Flash attention (causal), fp32 — unchanged from round 2 (next round's target)
// ---------------------------------------------------------------------------
#define FLASH_SMEM_BYTES ((64 * 68 * 2 + 64 * 64) * 4)

__global__ __launch_bounds__(256)
void flash_kernel()
{
    extern __shared__ float sm[];
    float* QsT = sm;
    float* KP  = sm + 64 * 68;
    float* Vs  = sm + 2 * 64 * 68;

    const int tid = threadIdx.x;
    const int tx  = tid & 15;
    const int ty  = tid >> 4;
    const int bh  = blockIdx.y;
    const int b   = bh / H_;
    const int h   = bh % H_;
    const int qt  = (T_ / 64 - 1) - blockIdx.x;
    const int q0  = qt * 64;
    const long rowbase = (long)b * T_;
    const int qoff = h * DH_;
    const int koff = C_ + h * DH_;
    const int voff = 2 * C_ + h * DH_;
    const float scale = 0.125f;

    #pragma unroll
    for (int it = 0; it < 4; it++) {
        int idx = tid + it * 256;
        int r   = idx >> 4;
        int d0  = (idx & 15) * 4;
        float4 v = *(const float4*)&g_qkv[(rowbase + q0 + r) * N3C_ + qoff + d0];
        QsT[(d0 + 0) * 68 + r] = v.x;
        QsT[(d0 + 1) * 68 + r] = v.y;
        QsT[(d0 + 2) * 68 + r] = v.z;
        QsT[(d0 + 3) * 68 + r] = v.w;
    }

    float o[4][4];
    float mrow[4], lrow[4];
    #pragma unroll
    for (int i = 0; i < 4; i++) {
        mrow[i] = -1e30f;
        lrow[i] = 0.f;
        #pragma unroll
        for (int j = 0; j < 4; j++) o[i][j] = 0.f;
    }

    for (int kt = 0; kt <= qt; kt++) {
        const int k0 = kt * 64;
        __syncthreads();

        #pragma unroll
        for (int it = 0; it < 4; it++) {
            int idx = tid + it * 256;
            int c   = idx >> 4;
            int d0  = (idx & 15) * 4;
            long grow = (rowbase + k0 + c) * N3C_;
            float4 kv = *(const float4*)&g_qkv[grow + koff + d0];
            KP[(d0 + 0) * 68 + c] = kv.x;
            KP[(d0 + 1) * 68 + c] = kv.y;
            KP[(d0 + 2) * 68 + c] = kv.z;
            KP[(d0 + 3) * 68 + c] = kv.w;
            *(float4*)&Vs[c * 64 + d0] = *(const float4*)&g_qkv[grow + voff + d0];
        }
        __syncthreads();

        float s[4][4];
        #pragma unroll
        for (int i = 0; i < 4; i++)
            #pragma unroll
            for (int j = 0; j < 4; j++) s[i][j] = 0.f;

        #pragma unroll 16
        for (int d = 0; d < 64; d++) {
            float4 aq = *(float4*)&QsT[d * 68 + ty * 4];
            float4 bq = *(float4*)&KP[d * 68 + tx * 4];
            float av[4] = {aq.x, aq.y, aq.z, aq.w};
            float bv[4] = {bq.x, bq.y, bq.z, bq.w};
            #pragma unroll
            for (int i = 0; i < 4; i++)
                #pragma unroll
                for (int j = 0; j < 4; j++)
                    s[i][j] = fmaf(av[i], bv[j], s[i][j]);
        }

        const bool diag = (kt == qt);
        #pragma unroll
        for (int i = 0; i < 4; i++) {
            #pragma unroll
            for (int j = 0; j < 4; j++) {
                s[i][j] *= scale;
                if (diag && (tx * 4 + j) > (ty * 4 + i)) s[i][j] = -1e30f;
            }
            float tm = fmaxf(fmaxf(s[i][0], s[i][1]), fmaxf(s[i][2], s[i][3]));
            #pragma unroll
            for (int off = 8; off > 0; off >>= 1)
                tm = fmaxf(tm, __shfl_xor_sync(0xffffffffu, tm, off, 16));
            float newm  = fmaxf(mrow[i], tm);
            float alpha = __expf(mrow[i] - newm);
            float ps = 0.f;
            #pragma unroll
            for (int j = 0; j < 4; j++) {
                s[i][j] = __expf(s[i][j] - newm);
                ps += s[i][j];
            }
            #pragma unroll
            for (int off = 8; off > 0; off >>= 1)
                ps += __shfl_xor_sync(0xffffffffu, ps, off, 16);
            lrow[i] = lrow[i] * alpha + ps;
            mrow[i] = newm;
            #pragma unroll
            for (int j = 0; j < 4; j++) o[i][j] *= alpha;
        }

        __syncthreads();

        #pragma unroll
        for (int i = 0; i < 4; i++)
            *(float4*)&KP[(ty * 4 + i) * 68 + tx * 4] =
                make_float4(s[i][0], s[i][1], s[i][2], s[i][3]);
        __syncthreads();

        #pragma unroll 8
        for (int c = 0; c < 64; c++) {
            float av[4];
            #pragma unroll
            for (int i = 0; i < 4; i++) av[i] = KP[(ty * 4 + i) * 68 + c];
            float4 bq = *(float4*)&Vs[c * 64 + tx * 4];
            float bv[4] = {bq.x, bq.y, bq.z, bq.w};
            #pragma unroll
            for (int i = 0; i < 4; i++)
                #pragma unroll
                for (int j = 0; j < 4; j++)
                    o[i][j] = fmaf(av[i], bv[j], o[i][j]);
        }
    }

    #pragma unroll
    for (int i = 0; i < 4; i++) {
        float inv = 1.f / lrow[i];
        long r = rowbase + q0 + ty * 4 + i;
        float4 v = make_float4(o[i][0] * inv, o[i][1] * inv,
                               o[i][2] * inv, o[i][3] * inv);
        *(float4*)&g_att[r * C_ + qoff + tx * 4] = v;
    }
}

// ---------------------------------------------------------------------------
extern "C" void kernel_launch(void* const* d_in, const int* in_sizes, int n_in,
                              void* d_out, int out_size)
{
    const float* x    = (const float*)d_in[0];
    const float* Wqkv = (const float*)d_in[1];
    const float* Wout = (const float*)d_in[2];
    float* out = (float*)d_out;

    float *qkv_p = nullptr, *att_p = nullptr;
    cudaGetSymbolAddress((void**)&qkv_p, g_qkv);
    cudaGetSymbolAddress((void**)&att_p, g_att);

    cudaFuncSetAttribute(gemm_bf16x2_kernel,
                         cudaFuncAttributeMaxDynamicSharedMemorySize, GEMM_SMEM);
    cudaFuncSetAttribute(flash_kernel,
                         cudaFuncAttributeMaxDynamicSharedMemorySize,
                         FLASH_SMEM_BYTES);

    dim3 blk(256);
    // 1) QKV projection (tensor cores, split-bf16)
    gemm_bf16x2_kernel<<<dim3(N3C_ / 128, M_ / 128), blk, GEMM_SMEM>>>(
        x, Wqkv, qkv_p, M_, N3C_, C_);
    // 2) causal flash attention
    flash_kernel<<<dim3(T_ / 64, B_ * H_), blk, FLASH_SMEM_BYTES>>>();
    // 3) output projection (tensor cores, split-bf16)
    gemm_bf16x2_kernel<<<dim3(C_ / 128, M_ / 128), blk, GEMM_SMEM>>>(
        att_p, Wout, out, M_, C_, C_);
}

// round 9
// speedup vs baseline: 2.6892x; 1.8112x over previous
#include <cuda_runtime.h>
#include <cuda_bf16.h>
#include <cstdint>

#define B_   2
#define T_   2048
#define C_   768
#define H_   12
#define DH_  64
#define M_   (B_ * T_)        // 4096 token rows
#define N3C_ (3 * C_)         // 2304

// Scratch (allocation-free rule: device globals)
__device__ float g_qkv[M_ * N3C_];   // [4096, 2304]
__device__ float g_att[M_ * C_];     // [4096, 768]

// ---------------------------------------------------------------------------
// Split-bf16 helpers
// ---------------------------------------------------------------------------
__device__ __forceinline__ void split2(float x, float y, uint32_t& hi, uint32_t& lo)
{
    __nv_bfloat16 hx = __float2bfloat16_rn(x);
    __nv_bfloat16 hy = __float2bfloat16_rn(y);
    float rx = x - __bfloat162float(hx);
    float ry = y - __bfloat162float(hy);
    __nv_bfloat162 H; H.x = hx; H.y = hy;
    __nv_bfloat162 L = __floats2bfloat162_rn(rx, ry);
    hi = *reinterpret_cast<uint32_t*>(&H);
    lo = *reinterpret_cast<uint32_t*>(&L);
}

__device__ __forceinline__ void lm4(uint32_t* r, uint32_t addr)
{
    asm volatile("ldmatrix.sync.aligned.m8n8.x4.shared.b16 {%0,%1,%2,%3}, [%4];"
                 : "=r"(r[0]), "=r"(r[1]), "=r"(r[2]), "=r"(r[3]) : "r"(addr));
}

__device__ __forceinline__ void lm4t(uint32_t* r, uint32_t addr)
{
    asm volatile("ldmatrix.sync.aligned.m8n8.x4.trans.shared.b16 {%0,%1,%2,%3}, [%4];"
                 : "=r"(r[0]), "=r"(r[1]), "=r"(r[2]), "=r"(r[3]) : "r"(addr));
}

__device__ __forceinline__ void mma16816(float* d, const uint32_t* a,
                                         uint32_t b0, uint32_t b1)
{
    asm volatile("mma.sync.aligned.m16n8k16.row.col.f32.bf16.bf16.f32 "
                 "{%0,%1,%2,%3}, {%4,%5,%6,%7}, {%8,%9}, {%0,%1,%2,%3};"
                 : "+f"(d[0]), "+f"(d[1]), "+f"(d[2]), "+f"(d[3])
                 : "r"(a[0]), "r"(a[1]), "r"(a[2]), "r"(a[3]), "r"(b0), "r"(b1));
}

// ---------------------------------------------------------------------------
// Tensor-core GEMM (validated round 3): C = A @ B, split-bf16
// ---------------------------------------------------------------------------
#define GEMM_SMEM 65536

__global__ __launch_bounds__(256, 2)
void gemm_bf16x2_kernel(const float* __restrict__ A, const float* __restrict__ Bm,
                        float* __restrict__ C, int M, int N, int K)
{
    extern __shared__ uint8_t smraw[];
    uint8_t* Ahi = smraw;
    uint8_t* Alo = smraw + 16384;
    uint8_t* Bhi = smraw + 32768;
    uint8_t* Blo = smraw + 49152;
    const uint32_t sbase = (uint32_t)__cvta_generic_to_shared(smraw);
    const uint32_t sAhi = sbase;
    const uint32_t sAlo = sbase + 16384;
    const uint32_t sBhi = sbase + 32768;
    const uint32_t sBlo = sbase + 49152;

    const int tid  = threadIdx.x;
    const int lane = tid & 31;
    const int warp = tid >> 5;
    const int wr   = warp >> 2;
    const int wc   = warp & 3;
    const int row0 = blockIdx.y * 128;
    const int col0 = blockIdx.x * 128;

    const int l7     = lane & 7;
    const int a_row  = wr * 64 + (lane & 15);
    const int a_chi  = lane >> 4;
    const int b_n    = wc * 32 + ((lane >> 4) << 3) + l7;
    const int b_ckb  = (lane >> 3) & 1;

    float acc[4][4][4];
    #pragma unroll
    for (int i = 0; i < 4; i++)
        #pragma unroll
        for (int j = 0; j < 4; j++)
            #pragma unroll
            for (int r = 0; r < 4; r++) acc[i][j][r] = 0.f;

    for (int k0 = 0; k0 < K; k0 += 32) {
        __syncthreads();
        #pragma unroll
        for (int i = 0; i < 4; i++) {
            int idx = tid + i * 256;
            int m   = idx >> 3;
            int cq  = idx & 7;
            float4 v = *(const float4*)&A[(size_t)(row0 + m) * K + k0 + cq * 4];
            uint32_t h0, l0, h1, l1;
            split2(v.x, v.y, h0, l0);
            split2(v.z, v.w, h1, l1);
            int c = cq >> 1, hb = cq & 1;
            uint32_t off = m * 128 + (((c ^ (m & 7))) << 4) + hb * 8;
            *(uint2*)(Ahi + off) = make_uint2(h0, h1);
            *(uint2*)(Alo + off) = make_uint2(l0, l1);
        }
        #pragma unroll
        for (int i = 0; i < 4; i++) {
            int idx = tid + i * 256;
            int n   = idx & 127;
            int kq  = idx >> 7;
            const float* bp = &Bm[(size_t)(k0 + kq * 4) * N + col0 + n];
            float f0 = bp[0];
            float f1 = bp[(size_t)N];
            float f2 = bp[(size_t)2 * N];
            float f3 = bp[(size_t)3 * N];
            uint32_t h0, l0, h1, l1;
            split2(f0, f1, h0, l0);
            split2(f2, f3, h1, l1);
            int c = kq >> 1, hb = kq & 1;
            uint32_t off = n * 128 + (((c ^ (n & 7))) << 4) + hb * 8;
            *(uint2*)(Bhi + off) = make_uint2(h0, h1);
            *(uint2*)(Blo + off) = make_uint2(l0, l1);
        }
        __syncthreads();

        #pragma unroll
        for (int ks = 0; ks < 2; ks++) {
            uint32_t bh[8], bl[8];
            #pragma unroll
            for (int np = 0; np < 2; np++) {
                int n = b_n + np * 16;
                uint32_t boff = n * 128 + (((ks * 2 + b_ckb) ^ l7) << 4);
                lm4(&bh[np * 4], sBhi + boff);
                lm4(&bl[np * 4], sBlo + boff);
            }
            #pragma unroll
            for (int mt = 0; mt < 4; mt++) {
                int row = a_row + mt * 16;
                uint32_t aoff = row * 128 + (((ks * 2 + a_chi) ^ l7) << 4);
                uint32_t ah[4], al[4];
                lm4(ah, sAhi + aoff);
                lm4(al, sAlo + aoff);
                #pragma unroll
                for (int nt = 0; nt < 4; nt++) {
                    int bi = (nt >> 1) * 4 + (nt & 1) * 2;
                    mma16816(acc[mt][nt], ah, bh[bi], bh[bi + 1]);
                    mma16816(acc[mt][nt], ah, bl[bi], bl[bi + 1]);
                    mma16816(acc[mt][nt], al, bh[bi], bh[bi + 1]);
                }
            }
        }
    }

    const int g  = lane >> 2;
    const int tg = lane & 3;
    #pragma unroll
    for (int mt = 0; mt < 4; mt++) {
        #pragma unroll
        for (int nt = 0; nt < 4; nt++) {
            int r = row0 + wr * 64 + mt * 16 + g;
            int c = col0 + wc * 32 + nt * 8 + tg * 2;
            *(float2*)&C[(size_t)r * N + c] =
                make_float2(acc[mt][nt][0], acc[mt][nt][1]);
            *(float2*)&C[(size_t)(r + 8) * N + c] =
                make_float2(acc[mt][nt][2], acc[mt][nt][3]);
        }
    }
}

// ---------------------------------------------------------------------------
// Tensor-core flash attention (causal), split-bf16 mma.
// Block: 128 Q-rows x 64 K-cols, 8 warps, warp tile m16 x n64 (FA2 style).
// Smem (64KB): Qhi/Qlo [128][64]bf16, Khi/Klo [64][64], Vhi/Vlo [64][64],
// all rows 128B with XOR-chunk swizzle for conflict-free ldmatrix.
// ---------------------------------------------------------------------------
#define FBM 128
#define FBN 64
#define FLASH_TC_SMEM 65536

__global__ __launch_bounds__(256)
void flash_tc_kernel()
{
    extern __shared__ uint8_t fsm[];
    const uint32_t sb  = (uint32_t)__cvta_generic_to_shared(fsm);
    const uint32_t sQhi = sb;
    const uint32_t sQlo = sb + 16384;
    const uint32_t sKhi = sb + 32768;
    const uint32_t sKlo = sb + 40960;
    const uint32_t sVhi = sb + 49152;
    const uint32_t sVlo = sb + 57344;

    const int tid  = threadIdx.x;
    const int lane = tid & 31;
    const int w    = tid >> 5;
    const int g    = lane >> 2;
    const int tg   = lane & 3;
    const int bh   = blockIdx.y;
    const int b    = bh / H_;
    const int h    = bh % H_;
    const int qt   = (T_ / FBM - 1) - blockIdx.x;   // heavy q-blocks first
    const int q0   = qt * FBM;
    const long rowbase = (long)b * T_;
    const int qoff = h * DH_;
    const int koff = C_ + h * DH_;
    const int voff = 2 * C_ + h * DH_;
    const float scale = 0.125f;

    // ---- load Q tile [128][64] -> Qhi/Qlo (swizzled) ----
    #pragma unroll
    for (int i = 0; i < 8; i++) {
        int idx = tid + i * 256;
        int m   = idx >> 4;
        int cq  = idx & 15;
        float4 v = *(const float4*)&g_qkv[(rowbase + q0 + m) * N3C_ + qoff + cq * 4];
        uint32_t h0, l0, h1, l1;
        split2(v.x, v.y, h0, l0);
        split2(v.z, v.w, h1, l1);
        int c = cq >> 1, hb = cq & 1;
        uint32_t off = m * 128 + (((c ^ (m & 7))) << 4) + hb * 8;
        *(uint2*)(fsm + off)         = make_uint2(h0, h1);
        *(uint2*)(fsm + 16384 + off) = make_uint2(l0, l1);
    }

    float sacc[8][4], oacc[8][4];
    float mr[2] = {-1e30f, -1e30f};
    float lr[2] = {0.f, 0.f};
    #pragma unroll
    for (int nt = 0; nt < 8; nt++)
        #pragma unroll
        for (int r = 0; r < 4; r++) oacc[nt][r] = 0.f;

    const int wrow0 = q0 + w * 16;            // warp's first global q row
    const int nkt   = (q0 + FBM) / FBN;       // 2*qt + 2 k-tiles

    for (int kt = 0; kt < nkt; kt++) {
        const int k0 = kt * FBN;
        __syncthreads();   // prior-iteration K/V reads complete

        // ---- load K,V tiles [64][64] -> smem split (swizzled) ----
        #pragma unroll
        for (int i = 0; i < 4; i++) {
            int idx = tid + i * 256;
            int m   = idx >> 4;
            int cq  = idx & 15;
            long grow = (rowbase + k0 + m) * N3C_;
            int c = cq >> 1, hb = cq & 1;
            uint32_t off = m * 128 + (((c ^ (m & 7))) << 4) + hb * 8;
            float4 kv = *(const float4*)&g_qkv[grow + koff + cq * 4];
            uint32_t h0, l0, h1, l1;
            split2(kv.x, kv.y, h0, l0);
            split2(kv.z, kv.w, h1, l1);
            *(uint2*)(fsm + 32768 + off) = make_uint2(h0, h1);
            *(uint2*)(fsm + 40960 + off) = make_uint2(l0, l1);
            float4 vv = *(const float4*)&g_qkv[grow + voff + cq * 4];
            split2(vv.x, vv.y, h0, l0);
            split2(vv.z, vv.w, h1, l1);
            *(uint2*)(fsm + 49152 + off) = make_uint2(h0, h1);
            *(uint2*)(fsm + 57344 + off) = make_uint2(l0, l1);
        }
        __syncthreads();

        if (k0 > wrow0 + 15) continue;   // tile fully above causal diag for warp

        // ---- S = Q @ K^T ----
        #pragma unroll
        for (int nt = 0; nt < 8; nt++)
            #pragma unroll
            for (int r = 0; r < 4; r++) sacc[nt][r] = 0.f;

        const int arow = w * 16 + (lane & 15);
        #pragma unroll
        for (int kk = 0; kk < 4; kk++) {
            uint32_t ah[4], al[4];
            uint32_t aoff = arow * 128 + (((2 * kk + (lane >> 4)) ^ (arow & 7)) << 4);
            lm4(ah, sQhi + aoff);
            lm4(al, sQlo + aoff);
            #pragma unroll
            for (int ng = 0; ng < 4; ng++) {
                int n = ng * 16 + ((lane >> 4) << 3) + (lane & 7);
                uint32_t boff = n * 128 +
                    (((2 * kk + ((lane >> 3) & 1)) ^ (n & 7)) << 4);
                uint32_t bhv[4], blv[4];
                lm4(bhv, sKhi + boff);
                lm4(blv, sKlo + boff);
                mma16816(sacc[2 * ng],     ah, bhv[0], bhv[1]);
                mma16816(sacc[2 * ng],     ah, blv[0], blv[1]);
                mma16816(sacc[2 * ng],     al, bhv[0], bhv[1]);
                mma16816(sacc[2 * ng + 1], ah, bhv[2], bhv[3]);
                mma16816(sacc[2 * ng + 1], ah, blv[2], blv[3]);
                mma16816(sacc[2 * ng + 1], al, bhv[2], bhv[3]);
            }
        }

        // ---- scale + causal mask + online softmax ----
        const bool maskt = (k0 + FBN - 1 > wrow0);
        #pragma unroll
        for (int r = 0; r < 2; r++) {
            const int grow_ = wrow0 + g + r * 8;
            float tmax = -1e30f;
            #pragma unroll
            for (int nt = 0; nt < 8; nt++) {
                float v0 = sacc[nt][r * 2]     * scale;
                float v1 = sacc[nt][r * 2 + 1] * scale;
                if (maskt) {
                    int col = k0 + nt * 8 + tg * 2;
                    if (col     > grow_) v0 = -1e30f;
                    if (col + 1 > grow_) v1 = -1e30f;
                }
                sacc[nt][r * 2]     = v0;
                sacc[nt][r * 2 + 1] = v1;
                tmax = fmaxf(tmax, fmaxf(v0, v1));
            }
            tmax = fmaxf(tmax, __shfl_xor_sync(0xffffffffu, tmax, 1));
            tmax = fmaxf(tmax, __shfl_xor_sync(0xffffffffu, tmax, 2));
            float newm  = fmaxf(mr[r], tmax);
            float alpha = __expf(mr[r] - newm);
            float sum = 0.f;
            #pragma unroll
            for (int nt = 0; nt < 8; nt++) {
                float e0 = __expf(sacc[nt][r * 2]     - newm);
                float e1 = __expf(sacc[nt][r * 2 + 1] - newm);
                sacc[nt][r * 2]     = e0;
                sacc[nt][r * 2 + 1] = e1;
                sum += e0 + e1;
            }
            sum += __shfl_xor_sync(0xffffffffu, sum, 1);
            sum += __shfl_xor_sync(0xffffffffu, sum, 2);
            lr[r] = lr[r] * alpha + sum;
            mr[r] = newm;
            #pragma unroll
            for (int nt = 0; nt < 8; nt++) {
                oacc[nt][r * 2]     *= alpha;
                oacc[nt][r * 2 + 1] *= alpha;
            }
        }

        // ---- O += P @ V  (P from registers, V via trans ldmatrix) ----
        #pragma unroll
        for (int ks = 0; ks < 4; ks++) {
            uint32_t pah[4], pal[4];
            split2(sacc[2 * ks][0],     sacc[2 * ks][1],     pah[0], pal[0]);
            split2(sacc[2 * ks][2],     sacc[2 * ks][3],     pah[1], pal[1]);
            split2(sacc[2 * ks + 1][0], sacc[2 * ks + 1][1], pah[2], pal[2]);
            split2(sacc[2 * ks + 1][2], sacc[2 * ks + 1][3], pah[3], pal[3]);
            const int krow = ks * 16 + (lane & 15);
            #pragma unroll
            for (int dg = 0; dg < 4; dg++) {
                int ch = dg * 2 + (lane >> 4);
                uint32_t vb = krow * 128 + (((ch ^ (krow & 7))) << 4);
                uint32_t vh[4], vl[4];
                lm4t(vh, sVhi + vb);
                lm4t(vl, sVlo + vb);
                mma16816(oacc[2 * dg],     pah, vh[0], vh[1]);
                mma16816(oacc[2 * dg],     pah, vl[0], vl[1]);
                mma16816(oacc[2 * dg],     pal, vh[0], vh[1]);
                mma16816(oacc[2 * dg + 1], pah, vh[2], vh[3]);
                mma16816(oacc[2 * dg + 1], pah, vl[2], vl[3]);
                mma16816(oacc[2 * dg + 1], pal, vh[2], vh[3]);
            }
        }
    }

    // ---- normalize + write g_att ----
    const float inv0 = 1.f / lr[0];
    const float inv1 = 1.f / lr[1];
    const long r0 = rowbase + wrow0 + g;
    #pragma unroll
    for (int nt = 0; nt < 8; nt++) {
        int c = qoff + nt * 8 + tg * 2;
        *(float2*)&g_att[r0 * C_ + c] =
            make_float2(oacc[nt][0] * inv0, oacc[nt][1] * inv0);
        *(float2*)&g_att[(r0 + 8) * C_ + c] =
            make_float2(oacc[nt][2] * inv1, oacc[nt][3] * inv1);
    }
}

// ---------------------------------------------------------------------------
extern "C" void kernel_launch(void* const* d_in, const int* in_sizes, int n_in,
                              void* d_out, int out_size)
{
    const float* x    = (const float*)d_in[0];
    const float* Wqkv = (const float*)d_in[1];
    const float* Wout = (const float*)d_in[2];
    float* out = (float*)d_out;

    float *qkv_p = nullptr, *att_p = nullptr;
    cudaGetSymbolAddress((void**)&qkv_p, g_qkv);
    cudaGetSymbolAddress((void**)&att_p, g_att);

    cudaFuncSetAttribute(gemm_bf16x2_kernel,
                         cudaFuncAttributeMaxDynamicSharedMemorySize, GEMM_SMEM);
    cudaFuncSetAttribute(flash_tc_kernel,
                         cudaFuncAttributeMaxDynamicSharedMemorySize, FLASH_TC_SMEM);

    dim3 blk(256);
    // 1) QKV projection (tensor cores, split-bf16)
    gemm_bf16x2_kernel<<<dim3(N3C_ / 128, M_ / 128), blk, GEMM_SMEM>>>(
        x, Wqkv, qkv_p, M_, N3C_, C_);
    // 2) causal flash attention (tensor cores, split-bf16)
    flash_tc_kernel<<<dim3(T_ / FBM, B_ * H_), blk, FLASH_TC_SMEM>>>();
    // 3) output projection (tensor cores, split-bf16)
    gemm_bf16x2_kernel<<<dim3(C_ / 128, M_ / 128), blk, GEMM_SMEM>>>(
        att_p, Wout, out, M_, C_, C_);
}

// round 10
// speedup vs baseline: 2.7561x; 1.0249x over previous
#include <cuda_runtime.h>
#include <cuda_bf16.h>
#include <cstdint>

#define B_   2
#define T_   2048
#define C_   768
#define H_   12
#define DH_  64
#define M_   (B_ * T_)        // 4096 token rows
#define N3C_ (3 * C_)         // 2304

// ---------------------------------------------------------------------------
// Scratch (allocation-free rule: device globals) — all split hi/lo bf16
// ---------------------------------------------------------------------------
__device__ __nv_bfloat16 g_xh[M_ * C_],     g_xl[M_ * C_];      // x split
__device__ __nv_bfloat16 g_wqT_h[N3C_ * C_], g_wqT_l[N3C_ * C_]; // Wqkv^T split
__device__ __nv_bfloat16 g_woT_h[C_ * C_],  g_woT_l[C_ * C_];   // Wout^T split
__device__ __nv_bfloat16 g_qkvh[M_ * N3C_], g_qkvl[M_ * N3C_];  // qkv split
__device__ __nv_bfloat16 g_atth[M_ * C_],   g_attl[M_ * C_];    // att out split

// ---------------------------------------------------------------------------
// Helpers
// ---------------------------------------------------------------------------
__device__ __forceinline__ void split2(float x, float y, uint32_t& hi, uint32_t& lo)
{
    __nv_bfloat16 hx = __float2bfloat16_rn(x);
    __nv_bfloat16 hy = __float2bfloat16_rn(y);
    float rx = x - __bfloat162float(hx);
    float ry = y - __bfloat162float(hy);
    __nv_bfloat162 H; H.x = hx; H.y = hy;
    __nv_bfloat162 L = __floats2bfloat162_rn(rx, ry);
    hi = *reinterpret_cast<uint32_t*>(&H);
    lo = *reinterpret_cast<uint32_t*>(&L);
}

__device__ __forceinline__ void lm4(uint32_t* r, uint32_t addr)
{
    asm volatile("ldmatrix.sync.aligned.m8n8.x4.shared.b16 {%0,%1,%2,%3}, [%4];"
                 : "=r"(r[0]), "=r"(r[1]), "=r"(r[2]), "=r"(r[3]) : "r"(addr));
}

__device__ __forceinline__ void lm4t(uint32_t* r, uint32_t addr)
{
    asm volatile("ldmatrix.sync.aligned.m8n8.x4.trans.shared.b16 {%0,%1,%2,%3}, [%4];"
                 : "=r"(r[0]), "=r"(r[1]), "=r"(r[2]), "=r"(r[3]) : "r"(addr));
}

__device__ __forceinline__ void mma16816(float* d, const uint32_t* a,
                                         uint32_t b0, uint32_t b1)
{
    asm volatile("mma.sync.aligned.m16n8k16.row.col.f32.bf16.bf16.f32 "
                 "{%0,%1,%2,%3}, {%4,%5,%6,%7}, {%8,%9}, {%0,%1,%2,%3};"
                 : "+f"(d[0]), "+f"(d[1]), "+f"(d[2]), "+f"(d[3])
                 : "r"(a[0]), "r"(a[1]), "r"(a[2]), "r"(a[3]), "r"(b0), "r"(b1));
}

__device__ __forceinline__ void cpa16(uint32_t dst, const void* src)
{
    asm volatile("cp.async.cg.shared.global [%0], [%1], 16;" :: "r"(dst), "l"(src));
}
__device__ __forceinline__ void cp_commit()
{
    asm volatile("cp.async.commit_group;");
}
__device__ __forceinline__ void cp_wait1()
{
    asm volatile("cp.async.wait_group 1;");
}

// ---------------------------------------------------------------------------
// One-shot converters
// ---------------------------------------------------------------------------
__global__ void split_flat_kernel(const float* __restrict__ src,
                                  __nv_bfloat16* __restrict__ hi,
                                  __nv_bfloat16* __restrict__ lo, int n4)
{
    int i = blockIdx.x * blockDim.x + threadIdx.x;
    if (i >= n4) return;
    float4 v = ((const float4*)src)[i];
    uint32_t h0, l0, h1, l1;
    split2(v.x, v.y, h0, l0);
    split2(v.z, v.w, h1, l1);
    ((uint2*)hi)[i] = make_uint2(h0, h1);
    ((uint2*)lo)[i] = make_uint2(l0, l1);
}

// src [R][N] fp32 -> dst [N][R] hi/lo bf16  (R,N multiples of 32)
__global__ void splitT_kernel(const float* __restrict__ src,
                              __nv_bfloat16* __restrict__ hiT,
                              __nv_bfloat16* __restrict__ loT,
                              int R, int N)
{
    __shared__ float t[32][33];
    const int c0 = blockIdx.x * 32, r0 = blockIdx.y * 32;
    const int tx = threadIdx.x, ty = threadIdx.y;   // (32,8)
    #pragma unroll
    for (int j = 0; j < 4; j++)
        t[ty + j * 8][tx] = src[(size_t)(r0 + ty + j * 8) * N + c0 + tx];
    __syncthreads();
    #pragma unroll
    for (int j = 0; j < 4; j++) {
        float v = t[tx][ty + j * 8];
        __nv_bfloat16 h = __float2bfloat16_rn(v);
        float r = v - __bfloat162float(h);
        size_t o = (size_t)(c0 + ty + j * 8) * R + r0 + tx;
        hiT[o] = h;
        loT[o] = __float2bfloat16_rn(r);
    }
}

// ---------------------------------------------------------------------------
// Pre-split bf16 GEMM: C[M,N] = (Ah+Al)[M,K] @ (Bh+Bl)^T  (B given as [N][K]).
// Block 128x128, BK=64, 3-stage cp.async pipeline (192KB smem, 1 CTA/SM).
// SPLIT_OUT: write hi/lo bf16 (for qkv) instead of fp32.
// ---------------------------------------------------------------------------
#define GEMM_STAGE 65536
#define GEMM_SMEM  (3 * GEMM_STAGE)

template<bool SPLIT_OUT>
__global__ __launch_bounds__(256, 1)
void gemm_pre_kernel(const __nv_bfloat16* __restrict__ Ah,
                     const __nv_bfloat16* __restrict__ Al,
                     const __nv_bfloat16* __restrict__ Bh,
                     const __nv_bfloat16* __restrict__ Bl,
                     float* __restrict__ C,
                     __nv_bfloat16* __restrict__ Ch,
                     __nv_bfloat16* __restrict__ Cl,
                     int M, int N, int K)
{
    extern __shared__ uint8_t smraw[];
    const uint32_t sb = (uint32_t)__cvta_generic_to_shared(smraw);

    const int tid  = threadIdx.x;
    const int lane = tid & 31;
    const int warp = tid >> 5;
    const int wr   = warp >> 2;
    const int wc   = warp & 3;
    const int row0 = blockIdx.y * 128;
    const int col0 = blockIdx.x * 128;

    const int l7    = lane & 7;
    const int a_row = wr * 64 + (lane & 15);
    const int a_chi = lane >> 4;
    const int b_n   = wc * 32 + ((lane >> 4) << 3) + l7;
    const int b_ckb = (lane >> 3) & 1;

    // per-thread load coords (4 chunks per tile, 4 tiles)
    const int lm = tid >> 3;          // base row 0..31 step handled by i
    const int lch = tid & 7;          // chunk 0..7

    float acc[4][4][4];
    #pragma unroll
    for (int i = 0; i < 4; i++)
        #pragma unroll
        for (int j = 0; j < 4; j++)
            #pragma unroll
            for (int r = 0; r < 4; r++) acc[i][j][r] = 0.f;

    const int nk = K >> 6;   // K/64

    // issue loads for stage s covering k0
    auto issue = [&](int s, int k0) {
        uint32_t base = sb + s * GEMM_STAGE;
        #pragma unroll
        for (int i = 0; i < 4; i++) {
            int m  = lm + i * 32;
            uint32_t sw = m * 128 + ((uint32_t)(lch ^ (m & 7)) << 4);
            const size_t ga = (size_t)(row0 + m) * K + k0 + lch * 8;
            const size_t gb = (size_t)(col0 + m) * K + k0 + lch * 8;
            cpa16(base + sw,         Ah + ga);
            cpa16(base + 16384 + sw, Al + ga);
            cpa16(base + 32768 + sw, Bh + gb);
            cpa16(base + 49152 + sw, Bl + gb);
        }
    };

    issue(0, 0);  cp_commit();
    issue(1, 64); cp_commit();

    for (int k = 0; k < nk; k++) {
        cp_wait1();
        __syncthreads();
        if (k + 2 < nk) issue((k + 2) % 3, (k + 2) * 64);
        cp_commit();

        const uint32_t st = sb + (k % 3) * GEMM_STAGE;
        #pragma unroll
        for (int kk = 0; kk < 4; kk++) {
            uint32_t bh[8], bl[8];
            #pragma unroll
            for (int np = 0; np < 2; np++) {
                int n = b_n + np * 16;
                uint32_t boff = n * 128 + (((2 * kk + b_ckb) ^ l7) << 4);
                lm4(&bh[np * 4], st + 32768 + boff);
                lm4(&bl[np * 4], st + 49152 + boff);
            }
            #pragma unroll
            for (int mt = 0; mt < 4; mt++) {
                int row = a_row + mt * 16;
                uint32_t aoff = row * 128 + (((2 * kk + a_chi) ^ l7) << 4);
                uint32_t ah[4], al[4];
                lm4(ah, st + aoff);
                lm4(al, st + 16384 + aoff);
                #pragma unroll
                for (int nt = 0; nt < 4; nt++) {
                    int bi = (nt >> 1) * 4 + (nt & 1) * 2;
                    mma16816(acc[mt][nt], ah, bh[bi], bh[bi + 1]);
                    mma16816(acc[mt][nt], ah, bl[bi], bl[bi + 1]);
                    mma16816(acc[mt][nt], al, bh[bi], bh[bi + 1]);
                }
            }
        }
    }

    const int g  = lane >> 2;
    const int tg = lane & 3;
    #pragma unroll
    for (int mt = 0; mt < 4; mt++) {
        #pragma unroll
        for (int nt = 0; nt < 4; nt++) {
            int r = row0 + wr * 64 + mt * 16 + g;
            int c = col0 + wc * 32 + nt * 8 + tg * 2;
            if (SPLIT_OUT) {
                uint32_t hh, ll;
                split2(acc[mt][nt][0], acc[mt][nt][1], hh, ll);
                *(uint32_t*)&Ch[(size_t)r * N + c] = hh;
                *(uint32_t*)&Cl[(size_t)r * N + c] = ll;
                split2(acc[mt][nt][2], acc[mt][nt][3], hh, ll);
                *(uint32_t*)&Ch[(size_t)(r + 8) * N + c] = hh;
                *(uint32_t*)&Cl[(size_t)(r + 8) * N + c] = ll;
            } else {
                *(float2*)&C[(size_t)r * N + c] =
                    make_float2(acc[mt][nt][0], acc[mt][nt][1]);
                *(float2*)&C[(size_t)(r + 8) * N + c] =
                    make_float2(acc[mt][nt][2], acc[mt][nt][3]);
            }
        }
    }
}

// ---------------------------------------------------------------------------
// Tensor-core flash attention (causal), split-bf16, pre-split inputs.
// Block: 128 Q-rows x 64 K-cols, 8 warps. Smem 64KB:
// Qh@0 Ql@16K (128x64), Kh@32K Kl@40K Vh@48K Vl@56K (64x64).
// ---------------------------------------------------------------------------
#define FBM 128
#define FBN 64
#define FLASH_TC_SMEM 65536

__global__ __launch_bounds__(256)
void flash_tc_kernel()
{
    extern __shared__ uint8_t fsm[];
    const uint32_t sb  = (uint32_t)__cvta_generic_to_shared(fsm);
    const uint32_t sQhi = sb;
    const uint32_t sQlo = sb + 16384;
    const uint32_t sKhi = sb + 32768;
    const uint32_t sKlo = sb + 40960;
    const uint32_t sVhi = sb + 49152;
    const uint32_t sVlo = sb + 57344;

    const int tid  = threadIdx.x;
    const int lane = tid & 31;
    const int w    = tid >> 5;
    const int g    = lane >> 2;
    const int tg   = lane & 3;
    const int bh   = blockIdx.y;
    const int b    = bh / H_;
    const int h    = bh % H_;
    const int qt   = (T_ / FBM - 1) - blockIdx.x;   // heavy q-blocks first
    const int q0   = qt * FBM;
    const long rowbase = (long)b * T_;
    const int qoff = h * DH_;
    const int koff = C_ + h * DH_;
    const int voff = 2 * C_ + h * DH_;
    const float scale = 0.125f;

    // ---- load Q tile [128][64] hi/lo (direct bf16, swizzled) ----
    #pragma unroll
    for (int i = 0; i < 8; i++) {
        int idx   = tid + i * 256;
        int tsel  = idx >> 10;            // 0=hi, 1=lo
        int local = idx & 1023;
        int m = local >> 3, ch = local & 7;
        const __nv_bfloat16* src = tsel ? g_qkvl : g_qkvh;
        uint4 v = *(const uint4*)&src[(rowbase + q0 + m) * (size_t)N3C_ + qoff + ch * 8];
        *(uint4*)(fsm + tsel * 16384 + m * 128 + (((ch ^ (m & 7))) << 4)) = v;
    }

    float sacc[8][4], oacc[8][4];
    float mr[2] = {-1e30f, -1e30f};
    float lr[2] = {0.f, 0.f};
    #pragma unroll
    for (int nt = 0; nt < 8; nt++)
        #pragma unroll
        for (int r = 0; r < 4; r++) oacc[nt][r] = 0.f;

    const int wrow0 = q0 + w * 16;
    const int nkt   = (q0 + FBM) / FBN;

    for (int kt = 0; kt < nkt; kt++) {
        const int k0 = kt * FBN;
        __syncthreads();

        // ---- load K,V tiles [64][64] hi/lo (direct bf16, swizzled) ----
        #pragma unroll
        for (int i = 0; i < 8; i++) {
            int idx   = tid + i * 256;
            int tsel  = idx >> 9;          // 0:Kh 1:Kl 2:Vh 3:Vl
            int local = idx & 511;
            int m = local >> 3, ch = local & 7;
            const __nv_bfloat16* src = (tsel & 1) ? g_qkvl : g_qkvh;
            int off_ = (tsel < 2) ? koff : voff;
            uint4 v = *(const uint4*)&src[(rowbase + k0 + m) * (size_t)N3C_ + off_ + ch * 8];
            *(uint4*)(fsm + 32768 + tsel * 8192 + m * 128 + (((ch ^ (m & 7))) << 4)) = v;
        }
        __syncthreads();

        if (k0 > wrow0 + 15) continue;

        // ---- S = Q @ K^T ----
        #pragma unroll
        for (int nt = 0; nt < 8; nt++)
            #pragma unroll
            for (int r = 0; r < 4; r++) sacc[nt][r] = 0.f;

        const int arow = w * 16 + (lane & 15);
        #pragma unroll
        for (int kk = 0; kk < 4; kk++) {
            uint32_t ah[4], al[4];
            uint32_t aoff = arow * 128 + (((2 * kk + (lane >> 4)) ^ (arow & 7)) << 4);
            lm4(ah, sQhi + aoff);
            lm4(al, sQlo + aoff);
            #pragma unroll
            for (int ng = 0; ng < 4; ng++) {
                int n = ng * 16 + ((lane >> 4) << 3) + (lane & 7);
                uint32_t boff = n * 128 +
                    (((2 * kk + ((lane >> 3) & 1)) ^ (n & 7)) << 4);
                uint32_t bhv[4], blv[4];
                lm4(bhv, sKhi + boff);
                lm4(blv, sKlo + boff);
                mma16816(sacc[2 * ng],     ah, bhv[0], bhv[1]);
                mma16816(sacc[2 * ng],     ah, blv[0], blv[1]);
                mma16816(sacc[2 * ng],     al, bhv[0], bhv[1]);
                mma16816(sacc[2 * ng + 1], ah, bhv[2], bhv[3]);
                mma16816(sacc[2 * ng + 1], ah, blv[2], blv[3]);
                mma16816(sacc[2 * ng + 1], al, bhv[2], bhv[3]);
            }
        }

        // ---- scale + causal mask + online softmax ----
        const bool maskt = (k0 + FBN - 1 > wrow0);
        #pragma unroll
        for (int r = 0; r < 2; r++) {
            const int grow_ = wrow0 + g + r * 8;
            float tmax = -1e30f;
            #pragma unroll
            for (int nt = 0; nt < 8; nt++) {
                float v0 = sacc[nt][r * 2]     * scale;
                float v1 = sacc[nt][r * 2 + 1] * scale;
                if (maskt) {
                    int col = k0 + nt * 8 + tg * 2;
                    if (col     > grow_) v0 = -1e30f;
                    if (col + 1 > grow_) v1 = -1e30f;
                }
                sacc[nt][r * 2]     = v0;
                sacc[nt][r * 2 + 1] = v1;
                tmax = fmaxf(tmax, fmaxf(v0, v1));
            }
            tmax = fmaxf(tmax, __shfl_xor_sync(0xffffffffu, tmax, 1));
            tmax = fmaxf(tmax, __shfl_xor_sync(0xffffffffu, tmax, 2));
            float newm  = fmaxf(mr[r], tmax);
            float alpha = __expf(mr[r] - newm);
            float sum = 0.f;
            #pragma unroll
            for (int nt = 0; nt < 8; nt++) {
                float e0 = __expf(sacc[nt][r * 2]     - newm);
                float e1 = __expf(sacc[nt][r * 2 + 1] - newm);
                sacc[nt][r * 2]     = e0;
                sacc[nt][r * 2 + 1] = e1;
                sum += e0 + e1;
            }
            sum += __shfl_xor_sync(0xffffffffu, sum, 1);
            sum += __shfl_xor_sync(0xffffffffu, sum, 2);
            lr[r] = lr[r] * alpha + sum;
            mr[r] = newm;
            #pragma unroll
            for (int nt = 0; nt < 8; nt++) {
                oacc[nt][r * 2]     *= alpha;
                oacc[nt][r * 2 + 1] *= alpha;
            }
        }

        // ---- O += P @ V ----
        #pragma unroll
        for (int ks = 0; ks < 4; ks++) {
            uint32_t pah[4], pal[4];
            split2(sacc[2 * ks][0],     sacc[2 * ks][1],     pah[0], pal[0]);
            split2(sacc[2 * ks][2],     sacc[2 * ks][3],     pah[1], pal[1]);
            split2(sacc[2 * ks + 1][0], sacc[2 * ks + 1][1], pah[2], pal[2]);
            split2(sacc[2 * ks + 1][2], sacc[2 * ks + 1][3], pah[3], pal[3]);
            const int krow = ks * 16 + (lane & 15);
            #pragma unroll
            for (int dg = 0; dg < 4; dg++) {
                int ch = dg * 2 + (lane >> 4);
                uint32_t vb = krow * 128 + (((ch ^ (krow & 7))) << 4);
                uint32_t vh[4], vl[4];
                lm4t(vh, sVhi + vb);
                lm4t(vl, sVlo + vb);
                mma16816(oacc[2 * dg],     pah, vh[0], vh[1]);
                mma16816(oacc[2 * dg],     pah, vl[0], vl[1]);
                mma16816(oacc[2 * dg],     pal, vh[0], vh[1]);
                mma16816(oacc[2 * dg + 1], pah, vh[2], vh[3]);
                mma16816(oacc[2 * dg + 1], pah, vl[2], vl[3]);
                mma16816(oacc[2 * dg + 1], pal, vh[2], vh[3]);
            }
        }
    }

    // ---- normalize + write split att ----
    const float inv0 = 1.f / lr[0];
    const float inv1 = 1.f / lr[1];
    const long r0 = rowbase + wrow0 + g;
    #pragma unroll
    for (int nt = 0; nt < 8; nt++) {
        int c = qoff + nt * 8 + tg * 2;
        uint32_t hh, ll;
        split2(oacc[nt][0] * inv0, oacc[nt][1] * inv0, hh, ll);
        *(uint32_t*)&g_atth[r0 * C_ + c] = hh;
        *(uint32_t*)&g_attl[r0 * C_ + c] = ll;
        split2(oacc[nt][2] * inv1, oacc[nt][3] * inv1, hh, ll);
        *(uint32_t*)&g_atth[(r0 + 8) * C_ + c] = hh;
        *(uint32_t*)&g_attl[(r0 + 8) * C_ + c] = ll;
    }
}

// ---------------------------------------------------------------------------
extern "C" void kernel_launch(void* const* d_in, const int* in_sizes, int n_in,
                              void* d_out, int out_size)
{
    const float* x    = (const float*)d_in[0];
    const float* Wqkv = (const float*)d_in[1];
    const float* Wout = (const float*)d_in[2];
    float* out = (float*)d_out;

    __nv_bfloat16 *xh, *xl, *wqh, *wql, *woh, *wol, *qh, *ql, *ath, *atl;
    cudaGetSymbolAddress((void**)&xh,  g_xh);
    cudaGetSymbolAddress((void**)&xl,  g_xl);
    cudaGetSymbolAddress((void**)&wqh, g_wqT_h);
    cudaGetSymbolAddress((void**)&wql, g_wqT_l);
    cudaGetSymbolAddress((void**)&woh, g_woT_h);
    cudaGetSymbolAddress((void**)&wol, g_woT_l);
    cudaGetSymbolAddress((void**)&qh,  g_qkvh);
    cudaGetSymbolAddress((void**)&ql,  g_qkvl);
    cudaGetSymbolAddress((void**)&ath, g_atth);
    cudaGetSymbolAddress((void**)&atl, g_attl);

    cudaFuncSetAttribute(gemm_pre_kernel<true>,
                         cudaFuncAttributeMaxDynamicSharedMemorySize, GEMM_SMEM);
    cudaFuncSetAttribute(gemm_pre_kernel<false>,
                         cudaFuncAttributeMaxDynamicSharedMemorySize, GEMM_SMEM);
    cudaFuncSetAttribute(flash_tc_kernel,
                         cudaFuncAttributeMaxDynamicSharedMemorySize, FLASH_TC_SMEM);

    dim3 blk(256);

    // 0) pre-split inputs
    split_flat_kernel<<<(M_ * C_ / 4 + 255) / 256, 256>>>(x, xh, xl, M_ * C_ / 4);
    splitT_kernel<<<dim3(N3C_ / 32, C_ / 32), dim3(32, 8)>>>(Wqkv, wqh, wql, C_, N3C_);
    splitT_kernel<<<dim3(C_ / 32, C_ / 32),  dim3(32, 8)>>>(Wout, woh, wol, C_, C_);

    // 1) QKV projection -> split qkv
    gemm_pre_kernel<true><<<dim3(N3C_ / 128, M_ / 128), blk, GEMM_SMEM>>>(
        xh, xl, wqh, wql, nullptr, qh, ql, M_, N3C_, C_);

    // 2) causal flash attention -> split att
    flash_tc_kernel<<<dim3(T_ / FBM, B_ * H_), blk, FLASH_TC_SMEM>>>();

    // 3) output projection -> fp32 out
    gemm_pre_kernel<false><<<dim3(C_ / 128, M_ / 128), blk, GEMM_SMEM>>>(
        ath, atl, woh, wol, out, nullptr, nullptr, M_, C_, C_);
}

// round 11
// speedup vs baseline: 2.9887x; 1.0844x over previous
#include <cuda_runtime.h>
#include <cuda_bf16.h>
#include <cstdint>

#define B_   2
#define T_   2048
#define C_   768
#define H_   12
#define DH_  64
#define M_   (B_ * T_)        // 4096 token rows
#define N3C_ (3 * C_)         // 2304

// ---------------------------------------------------------------------------
// Scratch (allocation-free rule: device globals) — all split hi/lo bf16
// ---------------------------------------------------------------------------
__device__ __nv_bfloat16 g_xh[M_ * C_],     g_xl[M_ * C_];      // x split
__device__ __nv_bfloat16 g_wqT_h[N3C_ * C_], g_wqT_l[N3C_ * C_]; // Wqkv^T split
__device__ __nv_bfloat16 g_woT_h[C_ * C_],  g_woT_l[C_ * C_];   // Wout^T split
__device__ __nv_bfloat16 g_qkvh[M_ * N3C_], g_qkvl[M_ * N3C_];  // qkv split
__device__ __nv_bfloat16 g_atth[M_ * C_],   g_attl[M_ * C_];    // att out split

// ---------------------------------------------------------------------------
// Helpers
// ---------------------------------------------------------------------------
__device__ __forceinline__ void split2(float x, float y, uint32_t& hi, uint32_t& lo)
{
    __nv_bfloat16 hx = __float2bfloat16_rn(x);
    __nv_bfloat16 hy = __float2bfloat16_rn(y);
    float rx = x - __bfloat162float(hx);
    float ry = y - __bfloat162float(hy);
    __nv_bfloat162 H; H.x = hx; H.y = hy;
    __nv_bfloat162 L = __floats2bfloat162_rn(rx, ry);
    hi = *reinterpret_cast<uint32_t*>(&H);
    lo = *reinterpret_cast<uint32_t*>(&L);
}

__device__ __forceinline__ void lm4(uint32_t* r, uint32_t addr)
{
    asm volatile("ldmatrix.sync.aligned.m8n8.x4.shared.b16 {%0,%1,%2,%3}, [%4];"
                 : "=r"(r[0]), "=r"(r[1]), "=r"(r[2]), "=r"(r[3]) : "r"(addr));
}

__device__ __forceinline__ void lm4t(uint32_t* r, uint32_t addr)
{
    asm volatile("ldmatrix.sync.aligned.m8n8.x4.trans.shared.b16 {%0,%1,%2,%3}, [%4];"
                 : "=r"(r[0]), "=r"(r[1]), "=r"(r[2]), "=r"(r[3]) : "r"(addr));
}

__device__ __forceinline__ void mma16816(float* d, const uint32_t* a,
                                         uint32_t b0, uint32_t b1)
{
    asm volatile("mma.sync.aligned.m16n8k16.row.col.f32.bf16.bf16.f32 "
                 "{%0,%1,%2,%3}, {%4,%5,%6,%7}, {%8,%9}, {%0,%1,%2,%3};"
                 : "+f"(d[0]), "+f"(d[1]), "+f"(d[2]), "+f"(d[3])
                 : "r"(a[0]), "r"(a[1]), "r"(a[2]), "r"(a[3]), "r"(b0), "r"(b1));
}

__device__ __forceinline__ void cpa16(uint32_t dst, const void* src)
{
    asm volatile("cp.async.cg.shared.global [%0], [%1], 16;" :: "r"(dst), "l"(src));
}
__device__ __forceinline__ void cp_commit()
{
    asm volatile("cp.async.commit_group;");
}
__device__ __forceinline__ void cp_wait0()
{
    asm volatile("cp.async.wait_group 0;");
}
__device__ __forceinline__ void cp_wait1()
{
    asm volatile("cp.async.wait_group 1;");
}

// ---------------------------------------------------------------------------
// One-shot converters
// ---------------------------------------------------------------------------
__global__ void split_flat_kernel(const float* __restrict__ src,
                                  __nv_bfloat16* __restrict__ hi,
                                  __nv_bfloat16* __restrict__ lo, int n4)
{
    int i = blockIdx.x * blockDim.x + threadIdx.x;
    if (i >= n4) return;
    float4 v = ((const float4*)src)[i];
    uint32_t h0, l0, h1, l1;
    split2(v.x, v.y, h0, l0);
    split2(v.z, v.w, h1, l1);
    ((uint2*)hi)[i] = make_uint2(h0, h1);
    ((uint2*)lo)[i] = make_uint2(l0, l1);
}

// src [R][N] fp32 -> dst [N][R] hi/lo bf16  (R,N multiples of 32)
__global__ void splitT_kernel(const float* __restrict__ src,
                              __nv_bfloat16* __restrict__ hiT,
                              __nv_bfloat16* __restrict__ loT,
                              int R, int N)
{
    __shared__ float t[32][33];
    const int c0 = blockIdx.x * 32, r0 = blockIdx.y * 32;
    const int tx = threadIdx.x, ty = threadIdx.y;   // (32,8)
    #pragma unroll
    for (int j = 0; j < 4; j++)
        t[ty + j * 8][tx] = src[(size_t)(r0 + ty + j * 8) * N + c0 + tx];
    __syncthreads();
    #pragma unroll
    for (int j = 0; j < 4; j++) {
        float v = t[tx][ty + j * 8];
        __nv_bfloat16 h = __float2bfloat16_rn(v);
        float r = v - __bfloat162float(h);
        size_t o = (size_t)(c0 + ty + j * 8) * R + r0 + tx;
        hiT[o] = h;
        loT[o] = __float2bfloat16_rn(r);
    }
}

// ---------------------------------------------------------------------------
// Pre-split bf16 GEMM: C[M,N] = (Ah+Al)[M,K] @ (Bh+Bl)^T  (B given as [N][K]).
// Block 128x128, BK=64, 3-stage cp.async pipeline (192KB smem, 1 CTA/SM).
// mma products issued acc-interleaved (no RAW chains).
// ---------------------------------------------------------------------------
#define GEMM_STAGE 65536
#define GEMM_SMEM  (3 * GEMM_STAGE)

template<bool SPLIT_OUT>
__global__ __launch_bounds__(256, 1)
void gemm_pre_kernel(const __nv_bfloat16* __restrict__ Ah,
                     const __nv_bfloat16* __restrict__ Al,
                     const __nv_bfloat16* __restrict__ Bh,
                     const __nv_bfloat16* __restrict__ Bl,
                     float* __restrict__ C,
                     __nv_bfloat16* __restrict__ Ch,
                     __nv_bfloat16* __restrict__ Cl,
                     int M, int N, int K)
{
    extern __shared__ uint8_t smraw[];
    const uint32_t sb = (uint32_t)__cvta_generic_to_shared(smraw);

    const int tid  = threadIdx.x;
    const int lane = tid & 31;
    const int warp = tid >> 5;
    const int wr   = warp >> 2;
    const int wc   = warp & 3;
    const int row0 = blockIdx.y * 128;
    const int col0 = blockIdx.x * 128;

    const int l7    = lane & 7;
    const int a_row = wr * 64 + (lane & 15);
    const int a_chi = lane >> 4;
    const int b_n   = wc * 32 + ((lane >> 4) << 3) + l7;
    const int b_ckb = (lane >> 3) & 1;

    const int lm = tid >> 3;
    const int lch = tid & 7;

    float acc[4][4][4];
    #pragma unroll
    for (int i = 0; i < 4; i++)
        #pragma unroll
        for (int j = 0; j < 4; j++)
            #pragma unroll
            for (int r = 0; r < 4; r++) acc[i][j][r] = 0.f;

    const int nk = K >> 6;

    auto issue = [&](int s, int k0) {
        uint32_t base = sb + s * GEMM_STAGE;
        #pragma unroll
        for (int i = 0; i < 4; i++) {
            int m  = lm + i * 32;
            uint32_t sw = m * 128 + ((uint32_t)(lch ^ (m & 7)) << 4);
            const size_t ga = (size_t)(row0 + m) * K + k0 + lch * 8;
            const size_t gb = (size_t)(col0 + m) * K + k0 + lch * 8;
            cpa16(base + sw,         Ah + ga);
            cpa16(base + 16384 + sw, Al + ga);
            cpa16(base + 32768 + sw, Bh + gb);
            cpa16(base + 49152 + sw, Bl + gb);
        }
    };

    issue(0, 0);  cp_commit();
    issue(1, 64); cp_commit();

    for (int k = 0; k < nk; k++) {
        cp_wait1();
        __syncthreads();
        if (k + 2 < nk) issue((k + 2) % 3, (k + 2) * 64);
        cp_commit();

        const uint32_t st = sb + (k % 3) * GEMM_STAGE;
        #pragma unroll
        for (int kk = 0; kk < 4; kk++) {
            uint32_t bh[8], bl[8];
            #pragma unroll
            for (int np = 0; np < 2; np++) {
                int n = b_n + np * 16;
                uint32_t boff = n * 128 + (((2 * kk + b_ckb) ^ l7) << 4);
                lm4(&bh[np * 4], st + 32768 + boff);
                lm4(&bl[np * 4], st + 49152 + boff);
            }
            #pragma unroll
            for (int mt = 0; mt < 4; mt++) {
                int row = a_row + mt * 16;
                uint32_t aoff = row * 128 + (((2 * kk + a_chi) ^ l7) << 4);
                uint32_t ah[4], al[4];
                lm4(ah, st + aoff);
                lm4(al, st + 16384 + aoff);
                // product-major, acc-interleaved: no back-to-back same-acc mma
                #pragma unroll
                for (int nt = 0; nt < 4; nt++) {
                    int bi = (nt >> 1) * 4 + (nt & 1) * 2;
                    mma16816(acc[mt][nt], ah, bh[bi], bh[bi + 1]);
                }
                #pragma unroll
                for (int nt = 0; nt < 4; nt++) {
                    int bi = (nt >> 1) * 4 + (nt & 1) * 2;
                    mma16816(acc[mt][nt], ah, bl[bi], bl[bi + 1]);
                }
                #pragma unroll
                for (int nt = 0; nt < 4; nt++) {
                    int bi = (nt >> 1) * 4 + (nt & 1) * 2;
                    mma16816(acc[mt][nt], al, bh[bi], bh[bi + 1]);
                }
            }
        }
    }

    const int g  = lane >> 2;
    const int tg = lane & 3;
    #pragma unroll
    for (int mt = 0; mt < 4; mt++) {
        #pragma unroll
        for (int nt = 0; nt < 4; nt++) {
            int r = row0 + wr * 64 + mt * 16 + g;
            int c = col0 + wc * 32 + nt * 8 + tg * 2;
            if (SPLIT_OUT) {
                uint32_t hh, ll;
                split2(acc[mt][nt][0], acc[mt][nt][1], hh, ll);
                *(uint32_t*)&Ch[(size_t)r * N + c] = hh;
                *(uint32_t*)&Cl[(size_t)r * N + c] = ll;
                split2(acc[mt][nt][2], acc[mt][nt][3], hh, ll);
                *(uint32_t*)&Ch[(size_t)(r + 8) * N + c] = hh;
                *(uint32_t*)&Cl[(size_t)(r + 8) * N + c] = ll;
            } else {
                *(float2*)&C[(size_t)r * N + c] =
                    make_float2(acc[mt][nt][0], acc[mt][nt][1]);
                *(float2*)&C[(size_t)(r + 8) * N + c] =
                    make_float2(acc[mt][nt][2], acc[mt][nt][3]);
            }
        }
    }
}

// ---------------------------------------------------------------------------
// Tensor-core flash attention (causal), split-bf16, pre-split inputs.
// Block: 128 Q-rows x 64 K-cols, 8 warps. cp.async double-buffered K/V.
// Smem 96KB: Qh@0 Ql@16K (128x64); KV buf0@32K, buf1@64K
//            (each: Kh +0, Kl +8K, Vh +16K, Vl +24K; 64x64 tiles).
// ---------------------------------------------------------------------------
#define FBM 128
#define FBN 64
#define FLASH_TC_SMEM (96 * 1024)

__global__ __launch_bounds__(256)
void flash_tc_kernel()
{
    extern __shared__ uint8_t fsm[];
    const uint32_t sb  = (uint32_t)__cvta_generic_to_shared(fsm);
    const uint32_t sQhi = sb;
    const uint32_t sQlo = sb + 16384;

    const int tid  = threadIdx.x;
    const int lane = tid & 31;
    const int w    = tid >> 5;
    const int g    = lane >> 2;
    const int tg   = lane & 3;
    const int bh   = blockIdx.y;
    const int b    = bh / H_;
    const int h    = bh % H_;
    const int qt   = (T_ / FBM - 1) - blockIdx.x;   // heavy q-blocks first
    const int q0   = qt * FBM;
    const long rowbase = (long)b * T_;
    const int qoff = h * DH_;
    const int koff = C_ + h * DH_;
    const int voff = 2 * C_ + h * DH_;
    const float scale = 0.125f;

    // per-thread K/V load coords (8 cpa16 per tile per thread)
    const int kv_tsel  = tid >> 6;            // base; full tsel = idx>>9
    // (computed inline below)

    auto issueKV = [&](int buf, int k0) {
        const uint32_t kvb = sb + 32768 + buf * 32768;
        #pragma unroll
        for (int i = 0; i < 8; i++) {
            int idx   = tid + i * 256;
            int tsel  = idx >> 9;            // 0:Kh 1:Kl 2:Vh 3:Vl
            int local = idx & 511;
            int m = local >> 3, ch = local & 7;
            const __nv_bfloat16* src = (tsel & 1) ? g_qkvl : g_qkvh;
            int off_ = (tsel < 2) ? koff : voff;
            cpa16(kvb + tsel * 8192 + m * 128 + (((ch ^ (m & 7))) << 4),
                  &src[(rowbase + k0 + m) * (size_t)N3C_ + off_ + ch * 8]);
        }
    };

    // ---- load Q tile [128][64] hi/lo (direct bf16, swizzled) ----
    #pragma unroll
    for (int i = 0; i < 8; i++) {
        int idx   = tid + i * 256;
        int tsel  = idx >> 10;            // 0=hi, 1=lo
        int local = idx & 1023;
        int m = local >> 3, ch = local & 7;
        const __nv_bfloat16* src = tsel ? g_qkvl : g_qkvh;
        uint4 v = *(const uint4*)&src[(rowbase + q0 + m) * (size_t)N3C_ + qoff + ch * 8];
        *(uint4*)(fsm + tsel * 16384 + m * 128 + (((ch ^ (m & 7))) << 4)) = v;
    }

    float sacc[8][4], oacc[8][4];
    float mr[2] = {-1e30f, -1e30f};
    float lr[2] = {0.f, 0.f};
    #pragma unroll
    for (int nt = 0; nt < 8; nt++)
        #pragma unroll
        for (int r = 0; r < 4; r++) oacc[nt][r] = 0.f;

    const int wrow0 = q0 + w * 16;
    const int nkt   = (q0 + FBM) / FBN;

    issueKV(0, 0);
    cp_commit();

    for (int kt = 0; kt < nkt; kt++) {
        const int k0 = kt * FBN;
        const int cur = kt & 1;
        const bool more = (kt + 1 < nkt);

        if (more) { issueKV(cur ^ 1, k0 + FBN); cp_commit(); }
        if (more) cp_wait1(); else cp_wait0();
        __syncthreads();

        const uint32_t sKhi = sb + 32768 + cur * 32768;
        const uint32_t sKlo = sKhi + 8192;
        const uint32_t sVhi = sKhi + 16384;
        const uint32_t sVlo = sKhi + 24576;

        if (k0 <= wrow0 + 15) {
            // ---- S = Q @ K^T ----
            #pragma unroll
            for (int nt = 0; nt < 8; nt++)
                #pragma unroll
                for (int r = 0; r < 4; r++) sacc[nt][r] = 0.f;

            const int arow = w * 16 + (lane & 15);
            #pragma unroll
            for (int kk = 0; kk < 4; kk++) {
                uint32_t ah[4], al[4];
                uint32_t aoff = arow * 128 + (((2 * kk + (lane >> 4)) ^ (arow & 7)) << 4);
                lm4(ah, sQhi + aoff);
                lm4(al, sQlo + aoff);
                #pragma unroll
                for (int ng = 0; ng < 4; ng++) {
                    int n = ng * 16 + ((lane >> 4) << 3) + (lane & 7);
                    uint32_t boff = n * 128 +
                        (((2 * kk + ((lane >> 3) & 1)) ^ (n & 7)) << 4);
                    uint32_t bhv[4], blv[4];
                    lm4(bhv, sKhi + boff);
                    lm4(blv, sKlo + boff);
                    // acc-interleaved product order (same per-acc sequence)
                    mma16816(sacc[2 * ng],     ah, bhv[0], bhv[1]);
                    mma16816(sacc[2 * ng + 1], ah, bhv[2], bhv[3]);
                    mma16816(sacc[2 * ng],     ah, blv[0], blv[1]);
                    mma16816(sacc[2 * ng + 1], ah, blv[2], blv[3]);
                    mma16816(sacc[2 * ng],     al, bhv[0], bhv[1]);
                    mma16816(sacc[2 * ng + 1], al, bhv[2], bhv[3]);
                }
            }

            // ---- scale + causal mask + online softmax ----
            const bool maskt = (k0 + FBN - 1 > wrow0);
            #pragma unroll
            for (int r = 0; r < 2; r++) {
                const int grow_ = wrow0 + g + r * 8;
                float tmax = -1e30f;
                #pragma unroll
                for (int nt = 0; nt < 8; nt++) {
                    float v0 = sacc[nt][r * 2]     * scale;
                    float v1 = sacc[nt][r * 2 + 1] * scale;
                    if (maskt) {
                        int col = k0 + nt * 8 + tg * 2;
                        if (col     > grow_) v0 = -1e30f;
                        if (col + 1 > grow_) v1 = -1e30f;
                    }
                    sacc[nt][r * 2]     = v0;
                    sacc[nt][r * 2 + 1] = v1;
                    tmax = fmaxf(tmax, fmaxf(v0, v1));
                }
                tmax = fmaxf(tmax, __shfl_xor_sync(0xffffffffu, tmax, 1));
                tmax = fmaxf(tmax, __shfl_xor_sync(0xffffffffu, tmax, 2));
                float newm  = fmaxf(mr[r], tmax);
                float alpha = __expf(mr[r] - newm);
                float sum = 0.f;
                #pragma unroll
                for (int nt = 0; nt < 8; nt++) {
                    float e0 = __expf(sacc[nt][r * 2]     - newm);
                    float e1 = __expf(sacc[nt][r * 2 + 1] - newm);
                    sacc[nt][r * 2]     = e0;
                    sacc[nt][r * 2 + 1] = e1;
                    sum += e0 + e1;
                }
                sum += __shfl_xor_sync(0xffffffffu, sum, 1);
                sum += __shfl_xor_sync(0xffffffffu, sum, 2);
                lr[r] = lr[r] * alpha + sum;
                mr[r] = newm;
                #pragma unroll
                for (int nt = 0; nt < 8; nt++) {
                    oacc[nt][r * 2]     *= alpha;
                    oacc[nt][r * 2 + 1] *= alpha;
                }
            }

            // ---- O += P @ V ----
            #pragma unroll
            for (int ks = 0; ks < 4; ks++) {
                uint32_t pah[4], pal[4];
                split2(sacc[2 * ks][0],     sacc[2 * ks][1],     pah[0], pal[0]);
                split2(sacc[2 * ks][2],     sacc[2 * ks][3],     pah[1], pal[1]);
                split2(sacc[2 * ks + 1][0], sacc[2 * ks + 1][1], pah[2], pal[2]);
                split2(sacc[2 * ks + 1][2], sacc[2 * ks + 1][3], pah[3], pal[3]);
                const int krow = ks * 16 + (lane & 15);
                #pragma unroll
                for (int dg = 0; dg < 4; dg++) {
                    int ch = dg * 2 + (lane >> 4);
                    uint32_t vb = krow * 128 + (((ch ^ (krow & 7))) << 4);
                    uint32_t vh[4], vl[4];
                    lm4t(vh, sVhi + vb);
                    lm4t(vl, sVlo + vb);
                    mma16816(oacc[2 * dg],     pah, vh[0], vh[1]);
                    mma16816(oacc[2 * dg + 1], pah, vh[2], vh[3]);
                    mma16816(oacc[2 * dg],     pah, vl[0], vl[1]);
                    mma16816(oacc[2 * dg + 1], pah, vl[2], vl[3]);
                    mma16816(oacc[2 * dg],     pal, vh[0], vh[1]);
                    mma16816(oacc[2 * dg + 1], pal, vh[2], vh[3]);
                }
            }
        }

        __syncthreads();   // all reads done before next issue overwrites buffer
    }

    // ---- normalize + write split att ----
    const float inv0 = 1.f / lr[0];
    const float inv1 = 1.f / lr[1];
    const long r0 = rowbase + wrow0 + g;
    #pragma unroll
    for (int nt = 0; nt < 8; nt++) {
        int c = qoff + nt * 8 + tg * 2;
        uint32_t hh, ll;
        split2(oacc[nt][0] * inv0, oacc[nt][1] * inv0, hh, ll);
        *(uint32_t*)&g_atth[r0 * C_ + c] = hh;
        *(uint32_t*)&g_attl[r0 * C_ + c] = ll;
        split2(oacc[nt][2] * inv1, oacc[nt][3] * inv1, hh, ll);
        *(uint32_t*)&g_atth[(r0 + 8) * C_ + c] = hh;
        *(uint32_t*)&g_attl[(r0 + 8) * C_ + c] = ll;
    }
}

// ---------------------------------------------------------------------------
extern "C" void kernel_launch(void* const* d_in, const int* in_sizes, int n_in,
                              void* d_out, int out_size)
{
    const float* x    = (const float*)d_in[0];
    const float* Wqkv = (const float*)d_in[1];
    const float* Wout = (const float*)d_in[2];
    float* out = (float*)d_out;

    __nv_bfloat16 *xh, *xl, *wqh, *wql, *woh, *wol, *qh, *ql, *ath, *atl;
    cudaGetSymbolAddress((void**)&xh,  g_xh);
    cudaGetSymbolAddress((void**)&xl,  g_xl);
    cudaGetSymbolAddress((void**)&wqh, g_wqT_h);
    cudaGetSymbolAddress((void**)&wql, g_wqT_l);
    cudaGetSymbolAddress((void**)&woh, g_woT_h);
    cudaGetSymbolAddress((void**)&wol, g_woT_l);
    cudaGetSymbolAddress((void**)&qh,  g_qkvh);
    cudaGetSymbolAddress((void**)&ql,  g_qkvl);
    cudaGetSymbolAddress((void**)&ath, g_atth);
    cudaGetSymbolAddress((void**)&atl, g_attl);

    cudaFuncSetAttribute(gemm_pre_kernel<true>,
                         cudaFuncAttributeMaxDynamicSharedMemorySize, GEMM_SMEM);
    cudaFuncSetAttribute(gemm_pre_kernel<false>,
                         cudaFuncAttributeMaxDynamicSharedMemorySize, GEMM_SMEM);
    cudaFuncSetAttribute(flash_tc_kernel,
                         cudaFuncAttributeMaxDynamicSharedMemorySize, FLASH_TC_SMEM);

    dim3 blk(256);

    // 0) pre-split inputs
    split_flat_kernel<<<(M_ * C_ / 4 + 255) / 256, 256>>>(x, xh, xl, M_ * C_ / 4);
    splitT_kernel<<<dim3(N3C_ / 32, C_ / 32), dim3(32, 8)>>>(Wqkv, wqh, wql, C_, N3C_);
    splitT_kernel<<<dim3(C_ / 32, C_ / 32),  dim3(32, 8)>>>(Wout, woh, wol, C_, C_);

    // 1) QKV projection -> split qkv
    gemm_pre_kernel<true><<<dim3(N3C_ / 128, M_ / 128), blk, GEMM_SMEM>>>(
        xh, xl, wqh, wql, nullptr, qh, ql, M_, N3C_, C_);

    // 2) causal flash attention -> split att
    flash_tc_kernel<<<dim3(T_ / FBM, B_ * H_), blk, FLASH_TC_SMEM>>>();

    // 3) output projection -> fp32 out
    gemm_pre_kernel<false><<<dim3(C_ / 128, M_ / 128), blk, GEMM_SMEM>>>(
        ath, atl, woh, wol, out, nullptr, nullptr, M_, C_, C_);
}